// round 2
// baseline (speedup 1.0000x reference)
#include <cuda_runtime.h>
#include <cstdint>

// Inputs (metadata order):
//   d_in[0] state           float32 [B, A, N, 3]
//   d_in[1] nodes_coords    float32 [P, 2]
//   d_in[2] adj             float32 [P, N]
//   d_in[3] node_last_visit int32   [B, A]
//   d_in[4] patrol_index    int32   [P]
// Output: float32 [B, A, N, 6]
//
// out[r, n, 0:3] = state[r, n, :]
// out[r, n, 3:5] = nodes_coords[nlv[r], :]
// out[r, n, 5]   = adj[patrol_index[nlv[r]], n]

__global__ __launch_bounds__(192)
void policy_gather_kernel(const float* __restrict__ state,
                          const float* __restrict__ coords,
                          const float* __restrict__ adj,
                          const int*   __restrict__ nlv,
                          const int*   __restrict__ pidx,
                          float* __restrict__ out,
                          int N) {
    const int row = blockIdx.x;
    const int t   = threadIdx.x;

    // Row-constant gathers (L1-resident, broadcast across the block).
    const int   v   = __ldg(nlv + row);
    const int   idx = __ldg(pidx + v);
    const float zx  = __ldg(coords + 2 * v);
    const float zy  = __ldg(coords + 2 * v + 1);

    const float* __restrict__ st = state + (size_t)row * N * 3;
    const float* __restrict__ ar = adj   + (size_t)idx * N;
    float* __restrict__ orow     = out   + (size_t)row * N * 6;

    const int total = N * 6;

    // Vector path requires 16B-aligned row base (true when N is even).
    if ((((uintptr_t)orow) & 0xF) == 0) {
        const int vec4 = total >> 2;
        float4* __restrict__ o4 = reinterpret_cast<float4*>(orow);

        for (int j = t; j < vec4; j += blockDim.x) {
            const int f = 4 * j;
            float vals[4];
            #pragma unroll
            for (int k = 0; k < 4; ++k) {
                const int ff = f + k;
                const int n  = ff / 6;        // node index
                const int c  = ff - 6 * n;    // component 0..5
                float val;
                if (c < 3)        val = __ldg(st + 3 * n + c);  // predicated LDG
                else if (c == 3)  val = zx;
                else if (c == 4)  val = zy;
                else              val = __ldg(ar + n);          // predicated LDG
                vals[k] = val;
            }
            o4[j] = make_float4(vals[0], vals[1], vals[2], vals[3]);
        }
        // Scalar tail (empty when total % 4 == 0).
        for (int j = (vec4 << 2) + t; j < total; j += blockDim.x) {
            const int n = j / 6;
            const int c = j - 6 * n;
            orow[j] = (c < 3) ? __ldg(st + 3 * n + c)
                    : (c == 3) ? zx
                    : (c == 4) ? zy
                    : __ldg(ar + n);
        }
    } else {
        // Fallback: fully scalar, still coalesced per float.
        for (int j = t; j < total; j += blockDim.x) {
            const int n = j / 6;
            const int c = j - 6 * n;
            orow[j] = (c < 3) ? __ldg(st + 3 * n + c)
                    : (c == 3) ? zx
                    : (c == 4) ? zy
                    : __ldg(ar + n);
        }
    }
}

extern "C" void kernel_launch(void* const* d_in, const int* in_sizes, int n_in,
                              void* d_out, int out_size) {
    const float* state  = (const float*)d_in[0];
    const float* coords = (const float*)d_in[1];
    const float* adj    = (const float*)d_in[2];
    const int*   nlv    = (const int*)d_in[3];
    const int*   pidx   = (const int*)d_in[4];
    float*       out    = (float*)d_out;

    const int BA = in_sizes[3];            // B * A rows
    const int P  = in_sizes[4];            // patrol nodes
    const int N  = in_sizes[2] / P;        // graph size (adj is [P, N])

    // 192 threads: ceil(375/192)=2 iterations at 97.7% lane efficiency for N=250.
    policy_gather_kernel<<<BA, 192>>>(state, coords, adj, nlv, pidx, out, N);
}

// round 3
// speedup vs baseline: 1.5990x; 1.5990x over previous
#include <cuda_runtime.h>
#include <cstdint>

// Inputs (metadata order):
//   d_in[0] state           float32 [B, A, N, 3]
//   d_in[1] nodes_coords    float32 [P, 2]
//   d_in[2] adj             float32 [P, N]
//   d_in[3] node_last_visit int32   [B, A]
//   d_in[4] patrol_index    int32   [P]
// Output: float32 [B, A, N, 6]
//
// out[r, n, 0:3] = state[r, n, :]
// out[r, n, 3:5] = nodes_coords[nlv[r], :]
// out[r, n, 5]   = adj[patrol_index[nlv[r]], n]

__global__ __launch_bounds__(128)
void policy_gather_kernel(const float* __restrict__ state,
                          const float* __restrict__ coords,
                          const float* __restrict__ adj,
                          const int*   __restrict__ nlv,
                          const int*   __restrict__ pidx,
                          float* __restrict__ out,
                          int N) {
    extern __shared__ float s_row[];   // N * 6 floats, output-row layout

    const int row = blockIdx.x;
    const int t   = threadIdx.x;

    // Row-constant gathers (L1/L2 resident, broadcast).
    const int   v   = __ldg(nlv + row);
    const int   idx = __ldg(pidx + v);
    const float zx  = __ldg(coords + 2 * v);
    const float zy  = __ldg(coords + 2 * v + 1);

    const float* __restrict__ st = state + (size_t)row * N * 3;   // 3000B*row -> 8B aligned
    const float* __restrict__ ar = adj   + (size_t)idx * N;       // 1000B*idx -> 8B aligned
    float* __restrict__ orow     = out   + (size_t)row * N * 6;   // 6000B*row -> 16B aligned

    const bool aligned8 = ((((uintptr_t)st) | ((uintptr_t)ar)) & 7) == 0;

    if (aligned8) {
        // Phase 1: one thread per node pair. 6 state floats + 2 adj floats in,
        // 12 smem floats out, all 64-bit ops.
        const int pairs = N >> 1;
        for (int p = t; p < pairs; p += blockDim.x) {
            const float2 s01 = __ldcs(reinterpret_cast<const float2*>(st + 6 * p));
            const float2 s23 = __ldcs(reinterpret_cast<const float2*>(st + 6 * p + 2));
            const float2 s45 = __ldcs(reinterpret_cast<const float2*>(st + 6 * p + 4));
            const float2 aa  = __ldg (reinterpret_cast<const float2*>(ar + 2 * p));

            float2* d = reinterpret_cast<float2*>(s_row + 12 * p);
            d[0] = make_float2(s01.x, s01.y);   // n=2p:   s0, s1
            d[1] = make_float2(s23.x, zx);      //         s2, zx
            d[2] = make_float2(zy,    aa.x);    //         zy, adj
            d[3] = make_float2(s23.y, s45.x);   // n=2p+1: s3, s4
            d[4] = make_float2(s45.y, zx);      //         s5, zx
            d[5] = make_float2(zy,    aa.y);    //         zy, adj
        }
        // Odd-N tail node.
        if ((N & 1) && t == 0) {
            const int n = N - 1;
            float* d = s_row + 6 * n;
            d[0] = st[3 * n + 0];
            d[1] = st[3 * n + 1];
            d[2] = st[3 * n + 2];
            d[3] = zx;
            d[4] = zy;
            d[5] = ar[n];
        }
    } else {
        // Scalar fallback (never taken for standard allocations).
        for (int n = t; n < N; n += blockDim.x) {
            float* d = s_row + 6 * n;
            d[0] = st[3 * n + 0];
            d[1] = st[3 * n + 1];
            d[2] = st[3 * n + 2];
            d[3] = zx;
            d[4] = zy;
            d[5] = ar[n];
        }
    }
    __syncthreads();

    // Phase 2: fully coalesced float4 streaming store (evict-first).
    const int total = N * 6;
    if ((((uintptr_t)orow) & 0xF) == 0) {
        const int vec4 = total >> 2;
        float4* __restrict__ o4 = reinterpret_cast<float4*>(orow);
        const float4* __restrict__ s4 = reinterpret_cast<const float4*>(s_row);
        for (int j = t; j < vec4; j += blockDim.x) {
            __stcs(o4 + j, s4[j]);
        }
        for (int j = (vec4 << 2) + t; j < total; j += blockDim.x) {
            __stcs(orow + j, s_row[j]);
        }
    } else {
        for (int j = t; j < total; j += blockDim.x) {
            __stcs(orow + j, s_row[j]);
        }
    }
}

extern "C" void kernel_launch(void* const* d_in, const int* in_sizes, int n_in,
                              void* d_out, int out_size) {
    const float* state  = (const float*)d_in[0];
    const float* coords = (const float*)d_in[1];
    const float* adj    = (const float*)d_in[2];
    const int*   nlv    = (const int*)d_in[3];
    const int*   pidx   = (const int*)d_in[4];
    float*       out    = (float*)d_out;

    const int BA = in_sizes[3];            // B * A rows
    const int P  = in_sizes[4];            // patrol nodes
    const int N  = in_sizes[2] / P;        // graph size (adj is [P, N])

    const size_t smem = (size_t)N * 6 * sizeof(float);
    policy_gather_kernel<<<BA, 128, smem>>>(state, coords, adj, nlv, pidx, out, N);
}